// round 8
// baseline (speedup 1.0000x reference)
#include <cuda_runtime.h>
#include <cstddef>
#include <cstdint>

// Problem constants (match reference)
#define ND   40000
#define NP   20000
#define RREL 4
#define E_DDI 200000
#define E_PDI 200000
#define FD   128
#define FP   256
#define FO   128

// Degree buffer layout (all stored as rsqrt(clip(deg,1)) after finalize)
#define OFF_OUT_DDI 0              // [4][ND]
#define OFF_IN_DDI  (4*ND)         // [4][ND]
#define OFF_OUT_PDI (8*ND)         // [NP]
#define OFF_IN_PDI  (8*ND + NP)    // [ND]
#define DEG_TOTAL   (8*ND + NP + ND)

// Scratch (static device globals: no allocation allowed)
__device__ float g_y[(size_t)RREL * ND * FO];  // per-relation transformed feats
__device__ float g_h1[(size_t)ND * FO];
__device__ float g_h2[(size_t)ND * FO];
__device__ float g_hp[(size_t)NP * FO];
__device__ float g_deg[DEG_TOTAL];

// ---------------------------------------------------------------------------
// Vector atomic add (sm_90+): 4 floats per red op
// ---------------------------------------------------------------------------
__device__ __forceinline__ void red_add_v4(float4* addr, float4 v) {
    asm volatile("red.global.add.v4.f32 [%0], {%1, %2, %3, %4};"
                 :: "l"(addr), "f"(v.x), "f"(v.y), "f"(v.z), "f"(v.w)
                 : "memory");
}

// tf32 split helpers (Markidis 3xTF32)
__device__ __forceinline__ uint32_t f2tf32(float v) {
    uint32_t r;
    asm("cvt.rna.tf32.f32 %0, %1;" : "=r"(r) : "f"(v));
    return r;
}
__device__ __forceinline__ void split_tf32(float v, uint32_t& hi, uint32_t& lo) {
    hi = f2tf32(v);
    lo = f2tf32(v - __uint_as_float(hi));
}

__device__ __forceinline__ void mma_tf32(float* c, const uint32_t* a,
                                         uint32_t b0, uint32_t b1) {
    asm volatile(
        "mma.sync.aligned.m16n8k8.row.col.f32.tf32.tf32.f32 "
        "{%0,%1,%2,%3}, {%4,%5,%6,%7}, {%8,%9}, {%0,%1,%2,%3};"
        : "+f"(c[0]), "+f"(c[1]), "+f"(c[2]), "+f"(c[3])
        : "r"(a[0]), "r"(a[1]), "r"(a[2]), "r"(a[3]), "r"(b0), "r"(b1));
}

// ---------------------------------------------------------------------------
// Degree computation
// ---------------------------------------------------------------------------
__global__ void count_ddi_kernel(const int* __restrict__ src,
                                 const int* __restrict__ dst) {
    int r = blockIdx.y;
    int e = blockIdx.x * blockDim.x + threadIdx.x;
    if (e >= E_DDI) return;
    int s = src[r * E_DDI + e];
    int d = dst[r * E_DDI + e];
    atomicAdd(&g_deg[OFF_OUT_DDI + r * ND + s], 1.0f);
    atomicAdd(&g_deg[OFF_IN_DDI  + r * ND + d], 1.0f);
}

__global__ void count_pdi_kernel(const int* __restrict__ src,
                                 const int* __restrict__ dst) {
    int e = blockIdx.x * blockDim.x + threadIdx.x;
    if (e >= E_PDI) return;
    atomicAdd(&g_deg[OFF_OUT_PDI + src[e]], 1.0f);
    atomicAdd(&g_deg[OFF_IN_PDI  + dst[e]], 1.0f);
}

__global__ void finalize_deg_kernel() {
    int i = blockIdx.x * blockDim.x + threadIdx.x;
    if (i >= DEG_TOTAL) return;
    float v = g_deg[i];
    g_deg[i] = rsqrtf(v < 1.0f ? 1.0f : v);
}

// ---------------------------------------------------------------------------
// Bias broadcast init: h[i][j] = sum_r bias[r][j] (+ bias2[j])
// ---------------------------------------------------------------------------
__global__ void bias_init_kernel(float* __restrict__ h,
                                 const float* __restrict__ bias, int bias_rows,
                                 const float* __restrict__ bias2, int M) {
    int idx = blockIdx.x * blockDim.x + threadIdx.x;   // one float4 each
    if (idx >= M * 32) return;
    int c4 = (idx & 31) * 4;
    float4 b = make_float4(0.f, 0.f, 0.f, 0.f);
    for (int rr = 0; rr < bias_rows; rr++) {
        b.x += __ldg(bias + rr * FO + c4 + 0);
        b.y += __ldg(bias + rr * FO + c4 + 1);
        b.z += __ldg(bias + rr * FO + c4 + 2);
        b.w += __ldg(bias + rr * FO + c4 + 3);
    }
    if (bias2) {
        b.x += __ldg(bias2 + c4 + 0);
        b.y += __ldg(bias2 + c4 + 1);
        b.z += __ldg(bias2 + c4 + 2);
        b.w += __ldg(bias2 + c4 + 3);
    }
    ((float4*)h)[idx] = b;
}

// ---------------------------------------------------------------------------
// Per-relation 3xTF32 tensor GEMM (v2: 512 threads / 16 warps for occupancy):
//   Y[r][M,128] = act(A[M,128]) @ W[r][128,128]
// Grid (ceil(M/128), RREL). Whole A-tile + W_r resident in dynamic smem.
// 16 warps in 8x2: warp = 16 rows x 64 cols, mma m16n8k8, 3xTF32.
// ---------------------------------------------------------------------------
#define AS_STRIDE 132
#define BS_STRIDE 136
#define GEMM_SMEM ((128 * AS_STRIDE + 128 * BS_STRIDE) * 4)

__global__ __launch_bounds__(512, 1)
void gemm_tf32_rel_kernel(const float* __restrict__ A,
                          const float* __restrict__ W,   // [RREL,128,128]
                          float* __restrict__ Y,          // [RREL,M,128]
                          int M, int do_relu) {
    extern __shared__ float smem[];
    float* As = smem;                      // [128][AS_STRIDE]
    float* Bs = smem + 128 * AS_STRIDE;    // [128][BS_STRIDE]

    const int tid = threadIdx.x;
    const int row0 = blockIdx.x * 128;
    const int r = blockIdx.y;

    // --- load A tile (relu optional) and W_r tile: 512 threads, 8 float4 each ---
    {
        const int ar = tid >> 2;            // 0..127
        const int ac = (tid & 3) * 32;      // 0,32,64,96
        const int gm = row0 + ar;
        #pragma unroll
        for (int i = 0; i < 8; i++) {
            float4 v = make_float4(0.f, 0.f, 0.f, 0.f);
            if (gm < M)
                v = __ldg((const float4*)(A + (size_t)gm * 128 + ac) + i);
            if (do_relu) {
                v.x = fmaxf(v.x, 0.f); v.y = fmaxf(v.y, 0.f);
                v.z = fmaxf(v.z, 0.f); v.w = fmaxf(v.w, 0.f);
            }
            *(float4*)&As[ar * AS_STRIDE + ac + i * 4] = v;
        }
        const float* Wr = W + (size_t)r * 128 * 128;
        #pragma unroll
        for (int i = 0; i < 8; i++) {
            float4 v = __ldg((const float4*)(Wr + (size_t)ar * 128 + ac) + i);
            *(float4*)&Bs[ar * BS_STRIDE + ac + i * 4] = v;
        }
    }
    __syncthreads();

    const int lane = tid & 31;
    const int g = lane >> 2;     // groupID
    const int tg = lane & 3;     // thread-in-group
    const int wid = tid >> 5;
    const int wm = (wid & 7) * 16;     // 8 warps along M: 16 rows each
    const int wn = (wid >> 3) * 64;    // 2 warps along N: 64 cols each

    float acc[8][4];
    #pragma unroll
    for (int nt = 0; nt < 8; nt++)
        #pragma unroll
        for (int q = 0; q < 4; q++) acc[nt][q] = 0.f;

    #pragma unroll
    for (int ks = 0; ks < 16; ks++) {
        const int k0 = ks * 8;
        // A fragment (hi/lo), one 16-row m-tile
        uint32_t ahi[4], alo[4];
        {
            float v0 = As[(wm + g)     * AS_STRIDE + k0 + tg];
            float v1 = As[(wm + g + 8) * AS_STRIDE + k0 + tg];
            float v2 = As[(wm + g)     * AS_STRIDE + k0 + tg + 4];
            float v3 = As[(wm + g + 8) * AS_STRIDE + k0 + tg + 4];
            split_tf32(v0, ahi[0], alo[0]);
            split_tf32(v1, ahi[1], alo[1]);
            split_tf32(v2, ahi[2], alo[2]);
            split_tf32(v3, ahi[3], alo[3]);
        }
        #pragma unroll
        for (int nt = 0; nt < 8; nt++) {
            const int n = wn + nt * 8 + g;
            float w0 = Bs[(k0 + tg)     * BS_STRIDE + n];
            float w1 = Bs[(k0 + tg + 4) * BS_STRIDE + n];
            uint32_t bh0, bl0, bh1, bl1;
            split_tf32(w0, bh0, bl0);
            split_tf32(w1, bh1, bl1);
            mma_tf32(acc[nt], ahi, bh0, bh1);
            mma_tf32(acc[nt], ahi, bl0, bl1);
            mma_tf32(acc[nt], alo, bh0, bh1);
        }
    }

    // --- store Y ---
    float* Yr = Y + (size_t)r * M * 128;
    const int rlo = row0 + wm + g;
    const int rhi = rlo + 8;
    #pragma unroll
    for (int nt = 0; nt < 8; nt++) {
        const int col = wn + nt * 8 + tg * 2;
        if (rlo < M)
            *(float2*)(Yr + (size_t)rlo * 128 + col) =
                make_float2(acc[nt][0], acc[nt][1]);
        if (rhi < M)
            *(float2*)(Yr + (size_t)rhi * 128 + col) =
                make_float2(acc[nt][2], acc[nt][3]);
    }
}

// ---------------------------------------------------------------------------
// DDI edge scatter: h[dst] += c * y[r][src];  c = rn_out[r][src]*rn_in[r][dst]
// 32 edges per warp, coalesced index staging + shfl broadcast.
// ---------------------------------------------------------------------------
__global__ void scatter_ddi_kernel(const float* __restrict__ y,
                                   float* __restrict__ h,
                                   const int* __restrict__ src,
                                   const int* __restrict__ dst) {
    const int r = blockIdx.y;
    const int lane = threadIdx.x & 31;
    const int warp = blockIdx.x * (blockDim.x >> 5) + (threadIdx.x >> 5);
    const int e0 = warp * 32;
    if (e0 >= E_DDI) return;
    const int n = (E_DDI - e0 < 32) ? (E_DDI - e0) : 32;

    int soff = 0, doff = 0;
    float c = 0.0f;
    if (lane < n) {
        int e = e0 + lane;
        int s = __ldg(src + (size_t)r * E_DDI + e);
        int d = __ldg(dst + (size_t)r * E_DDI + e);
        c = __ldg(g_deg + OFF_OUT_DDI + r * ND + s) *
            __ldg(g_deg + OFF_IN_DDI  + r * ND + d);
        soff = s * 32;     // float4 units within y[r]
        doff = d * 32;     // float4 units within h
    }

    const float4* __restrict__ yv = (const float4*)(y + (size_t)r * ND * 128);
    float4* hv = (float4*)h;

    if (n == 32) {
        #pragma unroll 4
        for (int j = 0; j < 32; j++) {
            int sj   = __shfl_sync(0xffffffffu, soff, j);
            int dj   = __shfl_sync(0xffffffffu, doff, j);
            float cj = __shfl_sync(0xffffffffu, c, j);
            float4 v = __ldg(yv + sj + lane);
            v.x *= cj; v.y *= cj; v.z *= cj; v.w *= cj;
            red_add_v4(hv + dj + lane, v);
        }
    } else {
        for (int j = 0; j < n; j++) {
            int sj   = __shfl_sync(0xffffffffu, soff, j);
            int dj   = __shfl_sync(0xffffffffu, doff, j);
            float cj = __shfl_sync(0xffffffffu, c, j);
            float4 v = __ldg(yv + sj + lane);
            v.x *= cj; v.y *= cj; v.z *= cj; v.w *= cj;
            red_add_v4(hv + dj + lane, v);
        }
    }
}

// PDI scatter: h1[dst] += hp[src] * rn_in_pdi[dst]  (src norm folded into GEMM)
__global__ void scatter_pdi_kernel(const int* __restrict__ src,
                                   const int* __restrict__ dst) {
    const int lane = threadIdx.x & 31;
    const int warp = blockIdx.x * (blockDim.x >> 5) + (threadIdx.x >> 5);
    const int e0 = warp * 32;
    if (e0 >= E_PDI) return;
    const int n = (E_PDI - e0 < 32) ? (E_PDI - e0) : 32;

    int soff = 0, doff = 0;
    float c = 0.0f;
    if (lane < n) {
        int e = e0 + lane;
        int s = __ldg(src + e);
        int d = __ldg(dst + e);
        c = __ldg(g_deg + OFF_IN_PDI + d);
        soff = s * 32;
        doff = d * 32;
    }

    const float4* __restrict__ hpv = (const float4*)g_hp;
    float4* h1v = (float4*)g_h1;

    #pragma unroll 4
    for (int j = 0; j < 32; j++) {
        if (j >= n) break;
        int sj   = __shfl_sync(0xffffffffu, soff, j);
        int dj   = __shfl_sync(0xffffffffu, doff, j);
        float cj = __shfl_sync(0xffffffffu, c, j);
        float4 v = __ldg(hpv + sj + lane);
        v.x *= cj; v.y *= cj; v.z *= cj; v.w *= cj;
        red_add_v4(h1v + dj + lane, v);
    }
}

// ---------------------------------------------------------------------------
// FFMA SGEMM (kept for the PDI branch, K=256):
// C[M,128] = A[M,K] @ B[K,128], optional per-row scale on A.
// ---------------------------------------------------------------------------
#define BM 128
#define BN 128
#define BK 16

__global__ __launch_bounds__(256, 2)
void gemm128_kernel(const float* __restrict__ A, const float* __restrict__ B,
                    float* __restrict__ C, int M, int K,
                    const float* __restrict__ row_scale) {
    __shared__ float As[2][BK][BM + 4];
    __shared__ float Bs[2][BK][BN];

    const int tid = threadIdx.x;
    const int tx = tid & 15;
    const int ty = tid >> 4;
    const int a_r = tid >> 2;
    const int a_c = (tid & 3) << 2;
    const int b_r = tid >> 5;
    const int b_c = (tid & 31) << 2;
    const int row0 = blockIdx.x * BM;

    float rs0 = 1.0f, rs1 = 1.0f;
    const int gm0 = row0 + a_r;
    const int gm1 = row0 + a_r + 64;
    if (row_scale) {
        if (gm0 < M) rs0 = __ldg(row_scale + gm0);
        if (gm1 < M) rs1 = __ldg(row_scale + gm1);
    }

    float acc[8][8];
    #pragma unroll
    for (int i = 0; i < 8; i++)
        #pragma unroll
        for (int j = 0; j < 8; j++) acc[i][j] = 0.0f;

    float4 pa0, pa1, pb0, pb1;

    pa0 = make_float4(0.f,0.f,0.f,0.f);
    pa1 = make_float4(0.f,0.f,0.f,0.f);
    if (gm0 < M) pa0 = __ldg((const float4*)(A + (size_t)gm0 * K + a_c));
    if (gm1 < M) pa1 = __ldg((const float4*)(A + (size_t)gm1 * K + a_c));
    pb0 = __ldg((const float4*)(B + (size_t)b_r * BN + b_c));
    pb1 = __ldg((const float4*)(B + (size_t)(b_r + 8) * BN + b_c));

    As[0][a_c + 0][a_r] = pa0.x * rs0;
    As[0][a_c + 1][a_r] = pa0.y * rs0;
    As[0][a_c + 2][a_r] = pa0.z * rs0;
    As[0][a_c + 3][a_r] = pa0.w * rs0;
    As[0][a_c + 0][a_r + 64] = pa1.x * rs1;
    As[0][a_c + 1][a_r + 64] = pa1.y * rs1;
    As[0][a_c + 2][a_r + 64] = pa1.z * rs1;
    As[0][a_c + 3][a_r + 64] = pa1.w * rs1;
    *(float4*)&Bs[0][b_r][b_c]     = pb0;
    *(float4*)&Bs[0][b_r + 8][b_c] = pb1;
    __syncthreads();

    const int ntiles = K / BK;
    int buf = 0;

    for (int t = 0; t < ntiles; t++) {
        const int k0n = (t + 1) * BK;
        if (t + 1 < ntiles) {
            pa0 = make_float4(0.f,0.f,0.f,0.f);
            pa1 = make_float4(0.f,0.f,0.f,0.f);
            if (gm0 < M) pa0 = __ldg((const float4*)(A + (size_t)gm0 * K + k0n + a_c));
            if (gm1 < M) pa1 = __ldg((const float4*)(A + (size_t)gm1 * K + k0n + a_c));
            pb0 = __ldg((const float4*)(B + (size_t)(k0n + b_r) * BN + b_c));
            pb1 = __ldg((const float4*)(B + (size_t)(k0n + b_r + 8) * BN + b_c));
        }

        #pragma unroll
        for (int k = 0; k < BK; k++) {
            float4 a0 = *(const float4*)&As[buf][k][ty * 8];
            float4 a1 = *(const float4*)&As[buf][k][ty * 8 + 4];
            float4 b0 = *(const float4*)&Bs[buf][k][tx * 8];
            float4 b1 = *(const float4*)&Bs[buf][k][tx * 8 + 4];
            float ra[8] = {a0.x, a0.y, a0.z, a0.w, a1.x, a1.y, a1.z, a1.w};
            float rb[8] = {b0.x, b0.y, b0.z, b0.w, b1.x, b1.y, b1.z, b1.w};
            #pragma unroll
            for (int i = 0; i < 8; i++)
                #pragma unroll
                for (int j = 0; j < 8; j++)
                    acc[i][j] = fmaf(ra[i], rb[j], acc[i][j]);
        }

        if (t + 1 < ntiles) {
            int nb = buf ^ 1;
            As[nb][a_c + 0][a_r] = pa0.x * rs0;
            As[nb][a_c + 1][a_r] = pa0.y * rs0;
            As[nb][a_c + 2][a_r] = pa0.z * rs0;
            As[nb][a_c + 3][a_r] = pa0.w * rs0;
            As[nb][a_c + 0][a_r + 64] = pa1.x * rs1;
            As[nb][a_c + 1][a_r + 64] = pa1.y * rs1;
            As[nb][a_c + 2][a_r + 64] = pa1.z * rs1;
            As[nb][a_c + 3][a_r + 64] = pa1.w * rs1;
            *(float4*)&Bs[nb][b_r][b_c]     = pb0;
            *(float4*)&Bs[nb][b_r + 8][b_c] = pb1;
            __syncthreads();
            buf = nb;
        }
    }

    #pragma unroll
    for (int i = 0; i < 8; i++) {
        int gm = row0 + ty * 8 + i;
        if (gm >= M) continue;
        float* cp = C + (size_t)gm * BN + tx * 8;
        *(float4*)(cp)     = make_float4(acc[i][0], acc[i][1], acc[i][2], acc[i][3]);
        *(float4*)(cp + 4) = make_float4(acc[i][4], acc[i][5], acc[i][6], acc[i][7]);
    }
}

// ---------------------------------------------------------------------------
// Launch
// ---------------------------------------------------------------------------
extern "C" void kernel_launch(void* const* d_in, const int* in_sizes, int n_in,
                              void* d_out, int out_size) {
    const float* x_d    = (const float*)d_in[0];
    const float* x_p    = (const float*)d_in[1];
    const float* W1     = (const float*)d_in[2];   // [4,128,128]
    const float* b1     = (const float*)d_in[3];   // [4,128]
    const float* W1_pdi = (const float*)d_in[4];   // [256,128]
    const float* b1_pdi = (const float*)d_in[5];   // [128]
    // d_in[6], d_in[7]: W1_ppi / b1_ppi -- dead code, unused
    const float* W2     = (const float*)d_in[8];
    const float* b2     = (const float*)d_in[9];
    const float* W3     = (const float*)d_in[10];
    const float* b3     = (const float*)d_in[11];
    const int* ddi_src  = (const int*)d_in[12];
    const int* ddi_dst  = (const int*)d_in[13];
    const int* pdi_src  = (const int*)d_in[14];
    const int* pdi_dst  = (const int*)d_in[15];
    // d_in[16], d_in[17]: ppi edges -- dead code, unused
    float* out = (float*)d_out;

    float *y, *h1, *h2, *hp, *deg;
    cudaGetSymbolAddress((void**)&y, g_y);
    cudaGetSymbolAddress((void**)&h1, g_h1);
    cudaGetSymbolAddress((void**)&h2, g_h2);
    cudaGetSymbolAddress((void**)&hp, g_hp);
    cudaGetSymbolAddress((void**)&deg, g_deg);

    cudaFuncSetAttribute(gemm_tf32_rel_kernel,
                         cudaFuncAttributeMaxDynamicSharedMemorySize, GEMM_SMEM);

    const float* rn_out_pdi = deg + OFF_OUT_PDI;

    const dim3 GEMM_TC((ND + 127) / 128, RREL);       // (313, 4)
    const int GEMM_BLOCKS_P = (NP + BM - 1) / BM;     // 157
    const int SCAT_BLKS = (E_DDI + 255) / 256;        // 32 edges/warp, 8 warps/blk
    const dim3 SCAT_DDI(SCAT_BLKS, RREL);
    const dim3 CNT_DDI((E_DDI + 255) / 256, RREL);
    const int BIAS_BLKS = (ND * 32 + 255) / 256;

    // --- degrees ---
    cudaMemsetAsync(deg, 0, (size_t)DEG_TOTAL * sizeof(float));
    count_ddi_kernel<<<CNT_DDI, 256>>>(ddi_src, ddi_dst);
    count_pdi_kernel<<<(E_PDI + 255) / 256, 256>>>(pdi_src, pdi_dst);
    finalize_deg_kernel<<<(DEG_TOTAL + 255) / 256, 256>>>();

    // --- Layer 1 ---
    gemm_tf32_rel_kernel<<<GEMM_TC, 512, GEMM_SMEM>>>(x_d, W1, y, ND, 0);
    gemm128_kernel<<<GEMM_BLOCKS_P, 256>>>(x_p, W1_pdi, hp, NP, FP, rn_out_pdi);
    bias_init_kernel<<<BIAS_BLKS, 256>>>(h1, b1, RREL, b1_pdi, ND);
    scatter_pdi_kernel<<<(E_PDI + 255) / 256, 256>>>(pdi_src, pdi_dst);
    scatter_ddi_kernel<<<SCAT_DDI, 256>>>(y, h1, ddi_src, ddi_dst);

    // --- Layer 2 ---  (relu of h1 folded into GEMM A-load)
    gemm_tf32_rel_kernel<<<GEMM_TC, 512, GEMM_SMEM>>>(h1, W2, y, ND, 1);
    bias_init_kernel<<<BIAS_BLKS, 256>>>(h2, b2, RREL, nullptr, ND);
    scatter_ddi_kernel<<<SCAT_DDI, 256>>>(y, h2, ddi_src, ddi_dst);

    // --- Layer 3 ---
    gemm_tf32_rel_kernel<<<GEMM_TC, 512, GEMM_SMEM>>>(h2, W3, y, ND, 1);
    bias_init_kernel<<<BIAS_BLKS, 256>>>(out, b3, RREL, nullptr, ND);
    scatter_ddi_kernel<<<SCAT_DDI, 256>>>(y, out, ddi_src, ddi_dst);
}

// round 11
// speedup vs baseline: 1.0299x; 1.0299x over previous
#include <cuda_runtime.h>
#include <cstddef>
#include <cstdint>

// Problem constants (match reference)
#define ND   40000
#define NP   20000
#define RREL 4
#define E_DDI 200000
#define E_PDI 200000
#define FD   128
#define FP   256
#define FO   128

// Degree buffer layout (all stored as rsqrt(clip(deg,1)) after finalize)
#define OFF_OUT_DDI 0              // [4][ND]
#define OFF_IN_DDI  (4*ND)         // [4][ND]
#define OFF_OUT_PDI (8*ND)         // [NP]
#define OFF_IN_PDI  (8*ND + NP)    // [ND]
#define DEG_TOTAL   (8*ND + NP + ND)

// Scratch (static device globals: no allocation allowed)
__device__ float g_y[(size_t)RREL * ND * FO];  // per-relation transformed feats
__device__ float g_h1[(size_t)ND * FO];
__device__ float g_h2[(size_t)ND * FO];
__device__ float g_hp[(size_t)NP * FO];
__device__ float g_deg[DEG_TOTAL];

// ---------------------------------------------------------------------------
// Vector atomic add (sm_90+): 4 floats per red op
// ---------------------------------------------------------------------------
__device__ __forceinline__ void red_add_v4(float4* addr, float4 v) {
    asm volatile("red.global.add.v4.f32 [%0], {%1, %2, %3, %4};"
                 :: "l"(addr), "f"(v.x), "f"(v.y), "f"(v.z), "f"(v.w)
                 : "memory");
}

// tf32 split helpers (Markidis 3xTF32)
__device__ __forceinline__ uint32_t f2tf32(float v) {
    uint32_t r;
    asm("cvt.rna.tf32.f32 %0, %1;" : "=r"(r) : "f"(v));
    return r;
}
__device__ __forceinline__ void split_tf32(float v, uint32_t& hi, uint32_t& lo) {
    hi = f2tf32(v);
    lo = f2tf32(v - __uint_as_float(hi));
}

__device__ __forceinline__ void mma_tf32(float* c, const uint32_t* a,
                                         uint32_t b0, uint32_t b1) {
    asm volatile(
        "mma.sync.aligned.m16n8k8.row.col.f32.tf32.tf32.f32 "
        "{%0,%1,%2,%3}, {%4,%5,%6,%7}, {%8,%9}, {%0,%1,%2,%3};"
        : "+f"(c[0]), "+f"(c[1]), "+f"(c[2]), "+f"(c[3])
        : "r"(a[0]), "r"(a[1]), "r"(a[2]), "r"(a[3]), "r"(b0), "r"(b1));
}

// ---------------------------------------------------------------------------
// Degree computation
// ---------------------------------------------------------------------------
__global__ void count_ddi_kernel(const int* __restrict__ src,
                                 const int* __restrict__ dst) {
    int r = blockIdx.y;
    int e = blockIdx.x * blockDim.x + threadIdx.x;
    if (e >= E_DDI) return;
    int s = src[r * E_DDI + e];
    int d = dst[r * E_DDI + e];
    atomicAdd(&g_deg[OFF_OUT_DDI + r * ND + s], 1.0f);
    atomicAdd(&g_deg[OFF_IN_DDI  + r * ND + d], 1.0f);
}

__global__ void count_pdi_kernel(const int* __restrict__ src,
                                 const int* __restrict__ dst) {
    int e = blockIdx.x * blockDim.x + threadIdx.x;
    if (e >= E_PDI) return;
    atomicAdd(&g_deg[OFF_OUT_PDI + src[e]], 1.0f);
    atomicAdd(&g_deg[OFF_IN_PDI  + dst[e]], 1.0f);
}

__global__ void finalize_deg_kernel() {
    int i = blockIdx.x * blockDim.x + threadIdx.x;
    if (i >= DEG_TOTAL) return;
    float v = g_deg[i];
    g_deg[i] = rsqrtf(v < 1.0f ? 1.0f : v);
}

// ---------------------------------------------------------------------------
// Bias broadcast init: h[i][j] = sum_r bias[r][j] (+ bias2[j])
// ---------------------------------------------------------------------------
__global__ void bias_init_kernel(float* __restrict__ h,
                                 const float* __restrict__ bias, int bias_rows,
                                 const float* __restrict__ bias2, int M) {
    int idx = blockIdx.x * blockDim.x + threadIdx.x;   // one float4 each
    if (idx >= M * 32) return;
    int c4 = (idx & 31) * 4;
    float4 b = make_float4(0.f, 0.f, 0.f, 0.f);
    for (int rr = 0; rr < bias_rows; rr++) {
        b.x += __ldg(bias + rr * FO + c4 + 0);
        b.y += __ldg(bias + rr * FO + c4 + 1);
        b.z += __ldg(bias + rr * FO + c4 + 2);
        b.w += __ldg(bias + rr * FO + c4 + 3);
    }
    if (bias2) {
        b.x += __ldg(bias2 + c4 + 0);
        b.y += __ldg(bias2 + c4 + 1);
        b.z += __ldg(bias2 + c4 + 2);
        b.w += __ldg(bias2 + c4 + 3);
    }
    ((float4*)h)[idx] = b;
}

// ---------------------------------------------------------------------------
// Per-relation 3xTF32 tensor GEMM (v3: 256-row CTA, 16 warps of 64m x 32n):
//   Y[r][M,128] = act(A[M,128]) @ W[r][128,128]
// Grid (ceil(M/256), RREL). A-tile [256,128] + W_r [128,128] in dynamic smem.
// 512 threads = 16 warps in 4x4: warp = 64 rows (mt=4) x 32 cols (nt=4).
// Overhead/MMA = 0.5 (R5-grade amortization) at 2x warps/SM vs R5.
// ---------------------------------------------------------------------------
#define CTA_M 256
#define AS_STRIDE 132
#define BS_STRIDE 136
#define GEMM_SMEM ((CTA_M * AS_STRIDE + 128 * BS_STRIDE) * 4)

__global__ __launch_bounds__(512, 1)
void gemm_tf32_rel_kernel(const float* __restrict__ A,
                          const float* __restrict__ W,   // [RREL,128,128]
                          float* __restrict__ Y,          // [RREL,M,128]
                          int M, int do_relu) {
    extern __shared__ float smem[];
    float* As = smem;                        // [CTA_M][AS_STRIDE]
    float* Bs = smem + CTA_M * AS_STRIDE;    // [128][BS_STRIDE]

    const int tid = threadIdx.x;
    const int row0 = blockIdx.x * CTA_M;
    const int r = blockIdx.y;

    // --- load A tile (256x128, relu optional): 512 threads, 16 float4 each ---
    {
        const int ar = tid >> 1;            // 0..255
        const int ac = (tid & 1) * 64;      // 0 or 64
        const int gm = row0 + ar;
        #pragma unroll
        for (int i = 0; i < 16; i++) {
            float4 v = make_float4(0.f, 0.f, 0.f, 0.f);
            if (gm < M)
                v = __ldg((const float4*)(A + (size_t)gm * 128 + ac) + i);
            if (do_relu) {
                v.x = fmaxf(v.x, 0.f); v.y = fmaxf(v.y, 0.f);
                v.z = fmaxf(v.z, 0.f); v.w = fmaxf(v.w, 0.f);
            }
            *(float4*)&As[ar * AS_STRIDE + ac + i * 4] = v;
        }
        // --- load W_r tile (128x128): 512 threads, 8 float4 each ---
        const int wr = tid >> 2;            // 0..127
        const int wc = (tid & 3) * 32;      // 0,32,64,96
        const float* Wr = W + (size_t)r * 128 * 128;
        #pragma unroll
        for (int i = 0; i < 8; i++) {
            float4 v = __ldg((const float4*)(Wr + (size_t)wr * 128 + wc) + i);
            *(float4*)&Bs[wr * BS_STRIDE + wc + i * 4] = v;
        }
    }
    __syncthreads();

    const int lane = tid & 31;
    const int g = lane >> 2;     // groupID
    const int tg = lane & 3;     // thread-in-group
    const int wid = tid >> 5;
    const int wm = (wid & 3) * 64;     // 4 warp positions along M: 64 rows each
    const int wn = (wid >> 2) * 32;    // 4 warp positions along N: 32 cols each

    float acc[4][4][4];          // [mt][nt][quad]
    #pragma unroll
    for (int mt = 0; mt < 4; mt++)
        #pragma unroll
        for (int nt = 0; nt < 4; nt++)
            #pragma unroll
            for (int q = 0; q < 4; q++) acc[mt][nt][q] = 0.f;

    #pragma unroll
    for (int ks = 0; ks < 16; ks++) {
        const int k0 = ks * 8;

        // B fragments for all 4 n-tiles (held in regs; reused by 4 m-tiles)
        uint32_t bh0[4], bl0[4], bh1[4], bl1[4];
        #pragma unroll
        for (int nt = 0; nt < 4; nt++) {
            const int n = wn + nt * 8 + g;
            float w0 = Bs[(k0 + tg)     * BS_STRIDE + n];
            float w1 = Bs[(k0 + tg + 4) * BS_STRIDE + n];
            split_tf32(w0, bh0[nt], bl0[nt]);
            split_tf32(w1, bh1[nt], bl1[nt]);
        }

        #pragma unroll
        for (int mt = 0; mt < 4; mt++) {
            const int m = wm + mt * 16;
            uint32_t ahi[4], alo[4];
            float v0 = As[(m + g)     * AS_STRIDE + k0 + tg];
            float v1 = As[(m + g + 8) * AS_STRIDE + k0 + tg];
            float v2 = As[(m + g)     * AS_STRIDE + k0 + tg + 4];
            float v3 = As[(m + g + 8) * AS_STRIDE + k0 + tg + 4];
            split_tf32(v0, ahi[0], alo[0]);
            split_tf32(v1, ahi[1], alo[1]);
            split_tf32(v2, ahi[2], alo[2]);
            split_tf32(v3, ahi[3], alo[3]);
            #pragma unroll
            for (int nt = 0; nt < 4; nt++) {
                mma_tf32(acc[mt][nt], ahi, bh0[nt], bh1[nt]);
                mma_tf32(acc[mt][nt], ahi, bl0[nt], bl1[nt]);
                mma_tf32(acc[mt][nt], alo, bh0[nt], bh1[nt]);
            }
        }
    }

    // --- store Y ---
    float* Yr = Y + (size_t)r * M * 128;
    #pragma unroll
    for (int mt = 0; mt < 4; mt++) {
        const int rlo = row0 + wm + mt * 16 + g;
        const int rhi = rlo + 8;
        #pragma unroll
        for (int nt = 0; nt < 4; nt++) {
            const int col = wn + nt * 8 + tg * 2;
            if (rlo < M)
                *(float2*)(Yr + (size_t)rlo * 128 + col) =
                    make_float2(acc[mt][nt][0], acc[mt][nt][1]);
            if (rhi < M)
                *(float2*)(Yr + (size_t)rhi * 128 + col) =
                    make_float2(acc[mt][nt][2], acc[mt][nt][3]);
        }
    }
}

// ---------------------------------------------------------------------------
// DDI edge scatter: h[dst] += c * y[r][src];  c = rn_out[r][src]*rn_in[r][dst]
// 32 edges per warp, coalesced index staging + shfl broadcast.
// ---------------------------------------------------------------------------
__global__ void scatter_ddi_kernel(const float* __restrict__ y,
                                   float* __restrict__ h,
                                   const int* __restrict__ src,
                                   const int* __restrict__ dst) {
    const int r = blockIdx.y;
    const int lane = threadIdx.x & 31;
    const int warp = blockIdx.x * (blockDim.x >> 5) + (threadIdx.x >> 5);
    const int e0 = warp * 32;
    if (e0 >= E_DDI) return;
    const int n = (E_DDI - e0 < 32) ? (E_DDI - e0) : 32;

    int soff = 0, doff = 0;
    float c = 0.0f;
    if (lane < n) {
        int e = e0 + lane;
        int s = __ldg(src + (size_t)r * E_DDI + e);
        int d = __ldg(dst + (size_t)r * E_DDI + e);
        c = __ldg(g_deg + OFF_OUT_DDI + r * ND + s) *
            __ldg(g_deg + OFF_IN_DDI  + r * ND + d);
        soff = s * 32;     // float4 units within y[r]
        doff = d * 32;     // float4 units within h
    }

    const float4* __restrict__ yv = (const float4*)(y + (size_t)r * ND * 128);
    float4* hv = (float4*)h;

    if (n == 32) {
        #pragma unroll 4
        for (int j = 0; j < 32; j++) {
            int sj   = __shfl_sync(0xffffffffu, soff, j);
            int dj   = __shfl_sync(0xffffffffu, doff, j);
            float cj = __shfl_sync(0xffffffffu, c, j);
            float4 v = __ldg(yv + sj + lane);
            v.x *= cj; v.y *= cj; v.z *= cj; v.w *= cj;
            red_add_v4(hv + dj + lane, v);
        }
    } else {
        for (int j = 0; j < n; j++) {
            int sj   = __shfl_sync(0xffffffffu, soff, j);
            int dj   = __shfl_sync(0xffffffffu, doff, j);
            float cj = __shfl_sync(0xffffffffu, c, j);
            float4 v = __ldg(yv + sj + lane);
            v.x *= cj; v.y *= cj; v.z *= cj; v.w *= cj;
            red_add_v4(hv + dj + lane, v);
        }
    }
}

// PDI scatter: h1[dst] += hp[src] * rn_in_pdi[dst]  (src norm folded into GEMM)
__global__ void scatter_pdi_kernel(const int* __restrict__ src,
                                   const int* __restrict__ dst) {
    const int lane = threadIdx.x & 31;
    const int warp = blockIdx.x * (blockDim.x >> 5) + (threadIdx.x >> 5);
    const int e0 = warp * 32;
    if (e0 >= E_PDI) return;
    const int n = (E_PDI - e0 < 32) ? (E_PDI - e0) : 32;

    int soff = 0, doff = 0;
    float c = 0.0f;
    if (lane < n) {
        int e = e0 + lane;
        int s = __ldg(src + e);
        int d = __ldg(dst + e);
        c = __ldg(g_deg + OFF_IN_PDI + d);
        soff = s * 32;
        doff = d * 32;
    }

    const float4* __restrict__ hpv = (const float4*)g_hp;
    float4* h1v = (float4*)g_h1;

    #pragma unroll 4
    for (int j = 0; j < 32; j++) {
        if (j >= n) break;
        int sj   = __shfl_sync(0xffffffffu, soff, j);
        int dj   = __shfl_sync(0xffffffffu, doff, j);
        float cj = __shfl_sync(0xffffffffu, c, j);
        float4 v = __ldg(hpv + sj + lane);
        v.x *= cj; v.y *= cj; v.z *= cj; v.w *= cj;
        red_add_v4(h1v + dj + lane, v);
    }
}

// ---------------------------------------------------------------------------
// FFMA SGEMM (kept for the PDI branch, K=256):
// C[M,128] = A[M,K] @ B[K,128], optional per-row scale on A.
// ---------------------------------------------------------------------------
#define BM 128
#define BN 128
#define BK 16

__global__ __launch_bounds__(256, 2)
void gemm128_kernel(const float* __restrict__ A, const float* __restrict__ B,
                    float* __restrict__ C, int M, int K,
                    const float* __restrict__ row_scale) {
    __shared__ float As[2][BK][BM + 4];
    __shared__ float Bs[2][BK][BN];

    const int tid = threadIdx.x;
    const int tx = tid & 15;
    const int ty = tid >> 4;
    const int a_r = tid >> 2;
    const int a_c = (tid & 3) << 2;
    const int b_r = tid >> 5;
    const int b_c = (tid & 31) << 2;
    const int row0 = blockIdx.x * BM;

    float rs0 = 1.0f, rs1 = 1.0f;
    const int gm0 = row0 + a_r;
    const int gm1 = row0 + a_r + 64;
    if (row_scale) {
        if (gm0 < M) rs0 = __ldg(row_scale + gm0);
        if (gm1 < M) rs1 = __ldg(row_scale + gm1);
    }

    float acc[8][8];
    #pragma unroll
    for (int i = 0; i < 8; i++)
        #pragma unroll
        for (int j = 0; j < 8; j++) acc[i][j] = 0.0f;

    float4 pa0, pa1, pb0, pb1;

    pa0 = make_float4(0.f,0.f,0.f,0.f);
    pa1 = make_float4(0.f,0.f,0.f,0.f);
    if (gm0 < M) pa0 = __ldg((const float4*)(A + (size_t)gm0 * K + a_c));
    if (gm1 < M) pa1 = __ldg((const float4*)(A + (size_t)gm1 * K + a_c));
    pb0 = __ldg((const float4*)(B + (size_t)b_r * BN + b_c));
    pb1 = __ldg((const float4*)(B + (size_t)(b_r + 8) * BN + b_c));

    As[0][a_c + 0][a_r] = pa0.x * rs0;
    As[0][a_c + 1][a_r] = pa0.y * rs0;
    As[0][a_c + 2][a_r] = pa0.z * rs0;
    As[0][a_c + 3][a_r] = pa0.w * rs0;
    As[0][a_c + 0][a_r + 64] = pa1.x * rs1;
    As[0][a_c + 1][a_r + 64] = pa1.y * rs1;
    As[0][a_c + 2][a_r + 64] = pa1.z * rs1;
    As[0][a_c + 3][a_r + 64] = pa1.w * rs1;
    *(float4*)&Bs[0][b_r][b_c]     = pb0;
    *(float4*)&Bs[0][b_r + 8][b_c] = pb1;
    __syncthreads();

    const int ntiles = K / BK;
    int buf = 0;

    for (int t = 0; t < ntiles; t++) {
        const int k0n = (t + 1) * BK;
        if (t + 1 < ntiles) {
            pa0 = make_float4(0.f,0.f,0.f,0.f);
            pa1 = make_float4(0.f,0.f,0.f,0.f);
            if (gm0 < M) pa0 = __ldg((const float4*)(A + (size_t)gm0 * K + k0n + a_c));
            if (gm1 < M) pa1 = __ldg((const float4*)(A + (size_t)gm1 * K + k0n + a_c));
            pb0 = __ldg((const float4*)(B + (size_t)(k0n + b_r) * BN + b_c));
            pb1 = __ldg((const float4*)(B + (size_t)(k0n + b_r + 8) * BN + b_c));
        }

        #pragma unroll
        for (int k = 0; k < BK; k++) {
            float4 a0 = *(const float4*)&As[buf][k][ty * 8];
            float4 a1 = *(const float4*)&As[buf][k][ty * 8 + 4];
            float4 b0 = *(const float4*)&Bs[buf][k][tx * 8];
            float4 b1 = *(const float4*)&Bs[buf][k][tx * 8 + 4];
            float ra[8] = {a0.x, a0.y, a0.z, a0.w, a1.x, a1.y, a1.z, a1.w};
            float rb[8] = {b0.x, b0.y, b0.z, b0.w, b1.x, b1.y, b1.z, b1.w};
            #pragma unroll
            for (int i = 0; i < 8; i++)
                #pragma unroll
                for (int j = 0; j < 8; j++)
                    acc[i][j] = fmaf(ra[i], rb[j], acc[i][j]);
        }

        if (t + 1 < ntiles) {
            int nb = buf ^ 1;
            As[nb][a_c + 0][a_r] = pa0.x * rs0;
            As[nb][a_c + 1][a_r] = pa0.y * rs0;
            As[nb][a_c + 2][a_r] = pa0.z * rs0;
            As[nb][a_c + 3][a_r] = pa0.w * rs0;
            As[nb][a_c + 0][a_r + 64] = pa1.x * rs1;
            As[nb][a_c + 1][a_r + 64] = pa1.y * rs1;
            As[nb][a_c + 2][a_r + 64] = pa1.z * rs1;
            As[nb][a_c + 3][a_r + 64] = pa1.w * rs1;
            *(float4*)&Bs[nb][b_r][b_c]     = pb0;
            *(float4*)&Bs[nb][b_r + 8][b_c] = pb1;
            __syncthreads();
            buf = nb;
        }
    }

    #pragma unroll
    for (int i = 0; i < 8; i++) {
        int gm = row0 + ty * 8 + i;
        if (gm >= M) continue;
        float* cp = C + (size_t)gm * BN + tx * 8;
        *(float4*)(cp)     = make_float4(acc[i][0], acc[i][1], acc[i][2], acc[i][3]);
        *(float4*)(cp + 4) = make_float4(acc[i][4], acc[i][5], acc[i][6], acc[i][7]);
    }
}

// ---------------------------------------------------------------------------
// Launch
// ---------------------------------------------------------------------------
extern "C" void kernel_launch(void* const* d_in, const int* in_sizes, int n_in,
                              void* d_out, int out_size) {
    const float* x_d    = (const float*)d_in[0];
    const float* x_p    = (const float*)d_in[1];
    const float* W1     = (const float*)d_in[2];   // [4,128,128]
    const float* b1     = (const float*)d_in[3];   // [4,128]
    const float* W1_pdi = (const float*)d_in[4];   // [256,128]
    const float* b1_pdi = (const float*)d_in[5];   // [128]
    // d_in[6], d_in[7]: W1_ppi / b1_ppi -- dead code, unused
    const float* W2     = (const float*)d_in[8];
    const float* b2     = (const float*)d_in[9];
    const float* W3     = (const float*)d_in[10];
    const float* b3     = (const float*)d_in[11];
    const int* ddi_src  = (const int*)d_in[12];
    const int* ddi_dst  = (const int*)d_in[13];
    const int* pdi_src  = (const int*)d_in[14];
    const int* pdi_dst  = (const int*)d_in[15];
    // d_in[16], d_in[17]: ppi edges -- dead code, unused
    float* out = (float*)d_out;

    float *y, *h1, *h2, *hp, *deg;
    cudaGetSymbolAddress((void**)&y, g_y);
    cudaGetSymbolAddress((void**)&h1, g_h1);
    cudaGetSymbolAddress((void**)&h2, g_h2);
    cudaGetSymbolAddress((void**)&hp, g_hp);
    cudaGetSymbolAddress((void**)&deg, g_deg);

    cudaFuncSetAttribute(gemm_tf32_rel_kernel,
                         cudaFuncAttributeMaxDynamicSharedMemorySize, GEMM_SMEM);

    const float* rn_out_pdi = deg + OFF_OUT_PDI;

    const dim3 GEMM_TC((ND + CTA_M - 1) / CTA_M, RREL);   // (157, 4)
    const int GEMM_BLOCKS_P = (NP + BM - 1) / BM;         // 157
    const int SCAT_BLKS = (E_DDI + 255) / 256;            // 32 edges/warp
    const dim3 SCAT_DDI(SCAT_BLKS, RREL);
    const dim3 CNT_DDI((E_DDI + 255) / 256, RREL);
    const int BIAS_BLKS = (ND * 32 + 255) / 256;

    // --- degrees ---
    cudaMemsetAsync(deg, 0, (size_t)DEG_TOTAL * sizeof(float));
    count_ddi_kernel<<<CNT_DDI, 256>>>(ddi_src, ddi_dst);
    count_pdi_kernel<<<(E_PDI + 255) / 256, 256>>>(pdi_src, pdi_dst);
    finalize_deg_kernel<<<(DEG_TOTAL + 255) / 256, 256>>>();

    // --- Layer 1 ---
    gemm_tf32_rel_kernel<<<GEMM_TC, 512, GEMM_SMEM>>>(x_d, W1, y, ND, 0);
    gemm128_kernel<<<GEMM_BLOCKS_P, 256>>>(x_p, W1_pdi, hp, NP, FP, rn_out_pdi);
    bias_init_kernel<<<BIAS_BLKS, 256>>>(h1, b1, RREL, b1_pdi, ND);
    scatter_pdi_kernel<<<(E_PDI + 255) / 256, 256>>>(pdi_src, pdi_dst);
    scatter_ddi_kernel<<<SCAT_DDI, 256>>>(y, h1, ddi_src, ddi_dst);

    // --- Layer 2 ---  (relu of h1 folded into GEMM A-load)
    gemm_tf32_rel_kernel<<<GEMM_TC, 512, GEMM_SMEM>>>(h1, W2, y, ND, 1);
    bias_init_kernel<<<BIAS_BLKS, 256>>>(h2, b2, RREL, nullptr, ND);
    scatter_ddi_kernel<<<SCAT_DDI, 256>>>(y, h2, ddi_src, ddi_dst);

    // --- Layer 3 ---
    gemm_tf32_rel_kernel<<<GEMM_TC, 512, GEMM_SMEM>>>(h2, W3, y, ND, 1);
    bias_init_kernel<<<BIAS_BLKS, 256>>>(out, b3, RREL, nullptr, ND);
    scatter_ddi_kernel<<<SCAT_DDI, 256>>>(y, out, ddi_src, ddi_dst);
}

// round 12
// speedup vs baseline: 1.2986x; 1.2609x over previous
#include <cuda_runtime.h>
#include <cuda_bf16.h>
#include <cstddef>
#include <cstdint>

// Problem constants (match reference)
#define ND   40000
#define NP   20000
#define RREL 4
#define E_DDI 200000
#define E_PDI 200000
#define FD   128
#define FP   256
#define FO   128

// Degree buffer layout (all stored as rsqrt(clip(deg,1)) after finalize)
#define OFF_OUT_DDI 0              // [4][ND]
#define OFF_IN_DDI  (4*ND)         // [4][ND]
#define OFF_OUT_PDI (8*ND)         // [NP]
#define OFF_IN_PDI  (8*ND + NP)    // [ND]
#define DEG_TOTAL   (8*ND + NP + ND)

// Scratch (static device globals: no allocation allowed)
__device__ float g_y[(size_t)RREL * ND * FO];  // per-relation transformed feats
__device__ float g_h1[(size_t)ND * FO];
__device__ float g_h2[(size_t)ND * FO];
__device__ float g_hp[(size_t)NP * FO];
__device__ float g_deg[DEG_TOTAL];

// ---------------------------------------------------------------------------
// Vector atomic add (sm_90+): 4 floats per red op
// ---------------------------------------------------------------------------
__device__ __forceinline__ void red_add_v4(float4* addr, float4 v) {
    asm volatile("red.global.add.v4.f32 [%0], {%1, %2, %3, %4};"
                 :: "l"(addr), "f"(v.x), "f"(v.y), "f"(v.z), "f"(v.w)
                 : "memory");
}

// bf16 split helpers: x = hi + lo, hi/lo bf16; residual ~x*2^-17
__device__ __forceinline__ void split2_bf16(float x, float y,
                                            uint32_t& hi, uint32_t& lo) {
    __nv_bfloat162 H = __floats2bfloat162_rn(x, y);
    float hx = __low2float(H), hy = __high2float(H);
    __nv_bfloat162 L = __floats2bfloat162_rn(x - hx, y - hy);
    hi = *reinterpret_cast<uint32_t*>(&H);
    lo = *reinterpret_cast<uint32_t*>(&L);
}

// m16n8k16 bf16 MMA (fp32 accum)
__device__ __forceinline__ void mma_bf16(float* c, const uint32_t* a,
                                         uint32_t b0, uint32_t b1) {
    asm volatile(
        "mma.sync.aligned.m16n8k16.row.col.f32.bf16.bf16.f32 "
        "{%0,%1,%2,%3}, {%4,%5,%6,%7}, {%8,%9}, {%0,%1,%2,%3};"
        : "+f"(c[0]), "+f"(c[1]), "+f"(c[2]), "+f"(c[3])
        : "r"(a[0]), "r"(a[1]), "r"(a[2]), "r"(a[3]), "r"(b0), "r"(b1));
}

// ---------------------------------------------------------------------------
// Degree computation
// ---------------------------------------------------------------------------
__global__ void count_ddi_kernel(const int* __restrict__ src,
                                 const int* __restrict__ dst) {
    int r = blockIdx.y;
    int e = blockIdx.x * blockDim.x + threadIdx.x;
    if (e >= E_DDI) return;
    int s = src[r * E_DDI + e];
    int d = dst[r * E_DDI + e];
    atomicAdd(&g_deg[OFF_OUT_DDI + r * ND + s], 1.0f);
    atomicAdd(&g_deg[OFF_IN_DDI  + r * ND + d], 1.0f);
}

__global__ void count_pdi_kernel(const int* __restrict__ src,
                                 const int* __restrict__ dst) {
    int e = blockIdx.x * blockDim.x + threadIdx.x;
    if (e >= E_PDI) return;
    atomicAdd(&g_deg[OFF_OUT_PDI + src[e]], 1.0f);
    atomicAdd(&g_deg[OFF_IN_PDI  + dst[e]], 1.0f);
}

__global__ void finalize_deg_kernel() {
    int i = blockIdx.x * blockDim.x + threadIdx.x;
    if (i >= DEG_TOTAL) return;
    float v = g_deg[i];
    g_deg[i] = rsqrtf(v < 1.0f ? 1.0f : v);
}

// ---------------------------------------------------------------------------
// Bias broadcast init: h[i][j] = sum_r bias[r][j] (+ bias2[j])
// ---------------------------------------------------------------------------
__global__ void bias_init_kernel(float* __restrict__ h,
                                 const float* __restrict__ bias, int bias_rows,
                                 const float* __restrict__ bias2, int M) {
    int idx = blockIdx.x * blockDim.x + threadIdx.x;   // one float4 each
    if (idx >= M * 32) return;
    int c4 = (idx & 31) * 4;
    float4 b = make_float4(0.f, 0.f, 0.f, 0.f);
    for (int rr = 0; rr < bias_rows; rr++) {
        b.x += __ldg(bias + rr * FO + c4 + 0);
        b.y += __ldg(bias + rr * FO + c4 + 1);
        b.z += __ldg(bias + rr * FO + c4 + 2);
        b.w += __ldg(bias + rr * FO + c4 + 3);
    }
    if (bias2) {
        b.x += __ldg(bias2 + c4 + 0);
        b.y += __ldg(bias2 + c4 + 1);
        b.z += __ldg(bias2 + c4 + 2);
        b.w += __ldg(bias2 + c4 + 3);
    }
    ((float4*)h)[idx] = b;
}

// ---------------------------------------------------------------------------
// Per-relation split-bf16 tensor GEMM (v4):
//   Y[r][M,128] = act(A[M,128]) @ W[r][128,128]
// 3-term bf16 split (AhiBhi + AhiBlo + AloBhi), mma m16n8k16 -> HALF the HMMA
// instructions of 3xTF32 (the measured sm_100 legacy-mma wall is instr-rate).
// Pre-split smem: As_hi/As_lo [256][136] bf16, Bs_hi/Bs_lo [128][136] bf16
// (n-major W). No cvt in mainloop; fragment LDS conflict-free (stride 136).
// Grid (ceil(M/256), RREL); 512 threads = 16 warps of 64m x 32n (mt=4, nt=4).
// ---------------------------------------------------------------------------
#define CTA_M 256
#define S2 136                       // bf16 stride (272B = 68 words, ==4 mod 32)
#define AS_H_OFF 0
#define AS_L_OFF (CTA_M * S2)                    // in bf16 units
#define BS_H_OFF (2 * CTA_M * S2)
#define BS_L_OFF (2 * CTA_M * S2 + 128 * S2)
#define GEMM_SMEM ((2 * CTA_M * S2 + 2 * 128 * S2) * 2)   // bytes = 208,896

__global__ __launch_bounds__(512, 1)
void gemm_bf16_rel_kernel(const float* __restrict__ A,
                          const float* __restrict__ W,   // [RREL,128,128]
                          float* __restrict__ Y,          // [RREL,M,128]
                          int M, int do_relu) {
    extern __shared__ __nv_bfloat16 smem[];
    __nv_bfloat16* AsH = smem + AS_H_OFF;
    __nv_bfloat16* AsL = smem + AS_L_OFF;
    __nv_bfloat16* BsH = smem + BS_H_OFF;
    __nv_bfloat16* BsL = smem + BS_L_OFF;

    const int tid = threadIdx.x;
    const int row0 = blockIdx.x * CTA_M;
    const int r = blockIdx.y;

    // --- load + split A tile (256x128): 512 threads, one row-half each ---
    {
        const int ar = tid >> 1;            // 0..255
        const int ac = (tid & 1) * 64;      // 0 or 64
        const int gm = row0 + ar;
        #pragma unroll
        for (int i = 0; i < 16; i++) {
            float4 v = make_float4(0.f, 0.f, 0.f, 0.f);
            if (gm < M)
                v = __ldg((const float4*)(A + (size_t)gm * 128 + ac) + i);
            if (do_relu) {
                v.x = fmaxf(v.x, 0.f); v.y = fmaxf(v.y, 0.f);
                v.z = fmaxf(v.z, 0.f); v.w = fmaxf(v.w, 0.f);
            }
            uint32_t h01, l01, h23, l23;
            split2_bf16(v.x, v.y, h01, l01);
            split2_bf16(v.z, v.w, h23, l23);
            const int off = ar * S2 + ac + i * 4;   // bf16 units, 8B-aligned
            *(uint2*)&AsH[off] = make_uint2(h01, h23);
            *(uint2*)&AsL[off] = make_uint2(l01, l23);
        }
    }
    // --- load + split + transpose W_r (128x128 -> n-major [n][k]) ---
    {
        const int n = tid & 127;            // output column
        const int kseg = tid >> 7;          // 0..3 -> k range of 32
        const float* Wr = W + (size_t)r * 128 * 128;
        #pragma unroll
        for (int kk = 0; kk < 32; kk += 2) {
            const int k = kseg * 32 + kk;
            float w0 = __ldg(Wr + (size_t)k * 128 + n);        // coalesced in n
            float w1 = __ldg(Wr + (size_t)(k + 1) * 128 + n);
            uint32_t h, l;
            split2_bf16(w0, w1, h, l);
            *(uint32_t*)&BsH[n * S2 + k] = h;   // 4B-aligned (k even)
            *(uint32_t*)&BsL[n * S2 + k] = l;
        }
    }
    __syncthreads();

    const int lane = tid & 31;
    const int g = lane >> 2;     // groupID
    const int tg = lane & 3;     // thread-in-group
    const int wid = tid >> 5;
    const int wm = (wid & 3) * 64;     // 4 warp positions along M: 64 rows each
    const int wn = (wid >> 2) * 32;    // 4 warp positions along N: 32 cols each

    float acc[4][4][4];          // [mt][nt][quad]
    #pragma unroll
    for (int mt = 0; mt < 4; mt++)
        #pragma unroll
        for (int nt = 0; nt < 4; nt++)
            #pragma unroll
            for (int q = 0; q < 4; q++) acc[mt][nt][q] = 0.f;

    #pragma unroll
    for (int ks = 0; ks < 8; ks++) {
        const int k0 = ks * 16;
        const int kc = k0 + 2 * tg;          // even -> 4B-aligned

        // B fragments for 4 n-tiles (reused by 4 m-tiles)
        uint32_t bh0[4], bh1[4], bl0[4], bl1[4];
        #pragma unroll
        for (int nt = 0; nt < 4; nt++) {
            const int n = wn + nt * 8 + g;
            bh0[nt] = *(const uint32_t*)&BsH[n * S2 + kc];
            bh1[nt] = *(const uint32_t*)&BsH[n * S2 + kc + 8];
            bl0[nt] = *(const uint32_t*)&BsL[n * S2 + kc];
            bl1[nt] = *(const uint32_t*)&BsL[n * S2 + kc + 8];
        }

        #pragma unroll
        for (int mt = 0; mt < 4; mt++) {
            const int m = wm + mt * 16;
            uint32_t ah[4], al[4];
            ah[0] = *(const uint32_t*)&AsH[(m + g)     * S2 + kc];
            ah[1] = *(const uint32_t*)&AsH[(m + g + 8) * S2 + kc];
            ah[2] = *(const uint32_t*)&AsH[(m + g)     * S2 + kc + 8];
            ah[3] = *(const uint32_t*)&AsH[(m + g + 8) * S2 + kc + 8];
            al[0] = *(const uint32_t*)&AsL[(m + g)     * S2 + kc];
            al[1] = *(const uint32_t*)&AsL[(m + g + 8) * S2 + kc];
            al[2] = *(const uint32_t*)&AsL[(m + g)     * S2 + kc + 8];
            al[3] = *(const uint32_t*)&AsL[(m + g + 8) * S2 + kc + 8];
            #pragma unroll
            for (int nt = 0; nt < 4; nt++) {
                mma_bf16(acc[mt][nt], ah, bh0[nt], bh1[nt]);
                mma_bf16(acc[mt][nt], ah, bl0[nt], bl1[nt]);
                mma_bf16(acc[mt][nt], al, bh0[nt], bh1[nt]);
            }
        }
    }

    // --- store Y ---
    float* Yr = Y + (size_t)r * M * 128;
    #pragma unroll
    for (int mt = 0; mt < 4; mt++) {
        const int rlo = row0 + wm + mt * 16 + g;
        const int rhi = rlo + 8;
        #pragma unroll
        for (int nt = 0; nt < 4; nt++) {
            const int col = wn + nt * 8 + tg * 2;
            if (rlo < M)
                *(float2*)(Yr + (size_t)rlo * 128 + col) =
                    make_float2(acc[mt][nt][0], acc[mt][nt][1]);
            if (rhi < M)
                *(float2*)(Yr + (size_t)rhi * 128 + col) =
                    make_float2(acc[mt][nt][2], acc[mt][nt][3]);
        }
    }
}

// ---------------------------------------------------------------------------
// DDI edge scatter: h[dst] += c * y[r][src];  c = rn_out[r][src]*rn_in[r][dst]
// 32 edges per warp, coalesced index staging + shfl broadcast.
// ---------------------------------------------------------------------------
__global__ void scatter_ddi_kernel(const float* __restrict__ y,
                                   float* __restrict__ h,
                                   const int* __restrict__ src,
                                   const int* __restrict__ dst) {
    const int r = blockIdx.y;
    const int lane = threadIdx.x & 31;
    const int warp = blockIdx.x * (blockDim.x >> 5) + (threadIdx.x >> 5);
    const int e0 = warp * 32;
    if (e0 >= E_DDI) return;
    const int n = (E_DDI - e0 < 32) ? (E_DDI - e0) : 32;

    int soff = 0, doff = 0;
    float c = 0.0f;
    if (lane < n) {
        int e = e0 + lane;
        int s = __ldg(src + (size_t)r * E_DDI + e);
        int d = __ldg(dst + (size_t)r * E_DDI + e);
        c = __ldg(g_deg + OFF_OUT_DDI + r * ND + s) *
            __ldg(g_deg + OFF_IN_DDI  + r * ND + d);
        soff = s * 32;     // float4 units within y[r]
        doff = d * 32;     // float4 units within h
    }

    const float4* __restrict__ yv = (const float4*)(y + (size_t)r * ND * 128);
    float4* hv = (float4*)h;

    if (n == 32) {
        #pragma unroll 4
        for (int j = 0; j < 32; j++) {
            int sj   = __shfl_sync(0xffffffffu, soff, j);
            int dj   = __shfl_sync(0xffffffffu, doff, j);
            float cj = __shfl_sync(0xffffffffu, c, j);
            float4 v = __ldg(yv + sj + lane);
            v.x *= cj; v.y *= cj; v.z *= cj; v.w *= cj;
            red_add_v4(hv + dj + lane, v);
        }
    } else {
        for (int j = 0; j < n; j++) {
            int sj   = __shfl_sync(0xffffffffu, soff, j);
            int dj   = __shfl_sync(0xffffffffu, doff, j);
            float cj = __shfl_sync(0xffffffffu, c, j);
            float4 v = __ldg(yv + sj + lane);
            v.x *= cj; v.y *= cj; v.z *= cj; v.w *= cj;
            red_add_v4(hv + dj + lane, v);
        }
    }
}

// PDI scatter: h1[dst] += hp[src] * rn_in_pdi[dst]  (src norm folded into GEMM)
__global__ void scatter_pdi_kernel(const int* __restrict__ src,
                                   const int* __restrict__ dst) {
    const int lane = threadIdx.x & 31;
    const int warp = blockIdx.x * (blockDim.x >> 5) + (threadIdx.x >> 5);
    const int e0 = warp * 32;
    if (e0 >= E_PDI) return;
    const int n = (E_PDI - e0 < 32) ? (E_PDI - e0) : 32;

    int soff = 0, doff = 0;
    float c = 0.0f;
    if (lane < n) {
        int e = e0 + lane;
        int s = __ldg(src + e);
        int d = __ldg(dst + e);
        c = __ldg(g_deg + OFF_IN_PDI + d);
        soff = s * 32;
        doff = d * 32;
    }

    const float4* __restrict__ hpv = (const float4*)g_hp;
    float4* h1v = (float4*)g_h1;

    #pragma unroll 4
    for (int j = 0; j < 32; j++) {
        if (j >= n) break;
        int sj   = __shfl_sync(0xffffffffu, soff, j);
        int dj   = __shfl_sync(0xffffffffu, doff, j);
        float cj = __shfl_sync(0xffffffffu, c, j);
        float4 v = __ldg(hpv + sj + lane);
        v.x *= cj; v.y *= cj; v.z *= cj; v.w *= cj;
        red_add_v4(h1v + dj + lane, v);
    }
}

// ---------------------------------------------------------------------------
// FFMA SGEMM (kept for the PDI branch, K=256):
// C[M,128] = A[M,K] @ B[K,128], optional per-row scale on A.
// ---------------------------------------------------------------------------
#define BM 128
#define BN 128
#define BK 16

__global__ __launch_bounds__(256, 2)
void gemm128_kernel(const float* __restrict__ A, const float* __restrict__ B,
                    float* __restrict__ C, int M, int K,
                    const float* __restrict__ row_scale) {
    __shared__ float As[2][BK][BM + 4];
    __shared__ float Bs[2][BK][BN];

    const int tid = threadIdx.x;
    const int tx = tid & 15;
    const int ty = tid >> 4;
    const int a_r = tid >> 2;
    const int a_c = (tid & 3) << 2;
    const int b_r = tid >> 5;
    const int b_c = (tid & 31) << 2;
    const int row0 = blockIdx.x * BM;

    float rs0 = 1.0f, rs1 = 1.0f;
    const int gm0 = row0 + a_r;
    const int gm1 = row0 + a_r + 64;
    if (row_scale) {
        if (gm0 < M) rs0 = __ldg(row_scale + gm0);
        if (gm1 < M) rs1 = __ldg(row_scale + gm1);
    }

    float acc[8][8];
    #pragma unroll
    for (int i = 0; i < 8; i++)
        #pragma unroll
        for (int j = 0; j < 8; j++) acc[i][j] = 0.0f;

    float4 pa0, pa1, pb0, pb1;

    pa0 = make_float4(0.f,0.f,0.f,0.f);
    pa1 = make_float4(0.f,0.f,0.f,0.f);
    if (gm0 < M) pa0 = __ldg((const float4*)(A + (size_t)gm0 * K + a_c));
    if (gm1 < M) pa1 = __ldg((const float4*)(A + (size_t)gm1 * K + a_c));
    pb0 = __ldg((const float4*)(B + (size_t)b_r * BN + b_c));
    pb1 = __ldg((const float4*)(B + (size_t)(b_r + 8) * BN + b_c));

    As[0][a_c + 0][a_r] = pa0.x * rs0;
    As[0][a_c + 1][a_r] = pa0.y * rs0;
    As[0][a_c + 2][a_r] = pa0.z * rs0;
    As[0][a_c + 3][a_r] = pa0.w * rs0;
    As[0][a_c + 0][a_r + 64] = pa1.x * rs1;
    As[0][a_c + 1][a_r + 64] = pa1.y * rs1;
    As[0][a_c + 2][a_r + 64] = pa1.z * rs1;
    As[0][a_c + 3][a_r + 64] = pa1.w * rs1;
    *(float4*)&Bs[0][b_r][b_c]     = pb0;
    *(float4*)&Bs[0][b_r + 8][b_c] = pb1;
    __syncthreads();

    const int ntiles = K / BK;
    int buf = 0;

    for (int t = 0; t < ntiles; t++) {
        const int k0n = (t + 1) * BK;
        if (t + 1 < ntiles) {
            pa0 = make_float4(0.f,0.f,0.f,0.f);
            pa1 = make_float4(0.f,0.f,0.f,0.f);
            if (gm0 < M) pa0 = __ldg((const float4*)(A + (size_t)gm0 * K + k0n + a_c));
            if (gm1 < M) pa1 = __ldg((const float4*)(A + (size_t)gm1 * K + k0n + a_c));
            pb0 = __ldg((const float4*)(B + (size_t)(k0n + b_r) * BN + b_c));
            pb1 = __ldg((const float4*)(B + (size_t)(k0n + b_r + 8) * BN + b_c));
        }

        #pragma unroll
        for (int k = 0; k < BK; k++) {
            float4 a0 = *(const float4*)&As[buf][k][ty * 8];
            float4 a1 = *(const float4*)&As[buf][k][ty * 8 + 4];
            float4 b0 = *(const float4*)&Bs[buf][k][tx * 8];
            float4 b1 = *(const float4*)&Bs[buf][k][tx * 8 + 4];
            float ra[8] = {a0.x, a0.y, a0.z, a0.w, a1.x, a1.y, a1.z, a1.w};
            float rb[8] = {b0.x, b0.y, b0.z, b0.w, b1.x, b1.y, b1.z, b1.w};
            #pragma unroll
            for (int i = 0; i < 8; i++)
                #pragma unroll
                for (int j = 0; j < 8; j++)
                    acc[i][j] = fmaf(ra[i], rb[j], acc[i][j]);
        }

        if (t + 1 < ntiles) {
            int nb = buf ^ 1;
            As[nb][a_c + 0][a_r] = pa0.x * rs0;
            As[nb][a_c + 1][a_r] = pa0.y * rs0;
            As[nb][a_c + 2][a_r] = pa0.z * rs0;
            As[nb][a_c + 3][a_r] = pa0.w * rs0;
            As[nb][a_c + 0][a_r + 64] = pa1.x * rs1;
            As[nb][a_c + 1][a_r + 64] = pa1.y * rs1;
            As[nb][a_c + 2][a_r + 64] = pa1.z * rs1;
            As[nb][a_c + 3][a_r + 64] = pa1.w * rs1;
            *(float4*)&Bs[nb][b_r][b_c]     = pb0;
            *(float4*)&Bs[nb][b_r + 8][b_c] = pb1;
            __syncthreads();
            buf = nb;
        }
    }

    #pragma unroll
    for (int i = 0; i < 8; i++) {
        int gm = row0 + ty * 8 + i;
        if (gm >= M) continue;
        float* cp = C + (size_t)gm * BN + tx * 8;
        *(float4*)(cp)     = make_float4(acc[i][0], acc[i][1], acc[i][2], acc[i][3]);
        *(float4*)(cp + 4) = make_float4(acc[i][4], acc[i][5], acc[i][6], acc[i][7]);
    }
}

// ---------------------------------------------------------------------------
// Launch
// ---------------------------------------------------------------------------
extern "C" void kernel_launch(void* const* d_in, const int* in_sizes, int n_in,
                              void* d_out, int out_size) {
    const float* x_d    = (const float*)d_in[0];
    const float* x_p    = (const float*)d_in[1];
    const float* W1     = (const float*)d_in[2];   // [4,128,128]
    const float* b1     = (const float*)d_in[3];   // [4,128]
    const float* W1_pdi = (const float*)d_in[4];   // [256,128]
    const float* b1_pdi = (const float*)d_in[5];   // [128]
    // d_in[6], d_in[7]: W1_ppi / b1_ppi -- dead code, unused
    const float* W2     = (const float*)d_in[8];
    const float* b2     = (const float*)d_in[9];
    const float* W3     = (const float*)d_in[10];
    const float* b3     = (const float*)d_in[11];
    const int* ddi_src  = (const int*)d_in[12];
    const int* ddi_dst  = (const int*)d_in[13];
    const int* pdi_src  = (const int*)d_in[14];
    const int* pdi_dst  = (const int*)d_in[15];
    // d_in[16], d_in[17]: ppi edges -- dead code, unused
    float* out = (float*)d_out;

    float *y, *h1, *h2, *hp, *deg;
    cudaGetSymbolAddress((void**)&y, g_y);
    cudaGetSymbolAddress((void**)&h1, g_h1);
    cudaGetSymbolAddress((void**)&h2, g_h2);
    cudaGetSymbolAddress((void**)&hp, g_hp);
    cudaGetSymbolAddress((void**)&deg, g_deg);

    cudaFuncSetAttribute(gemm_bf16_rel_kernel,
                         cudaFuncAttributeMaxDynamicSharedMemorySize, GEMM_SMEM);

    const float* rn_out_pdi = deg + OFF_OUT_PDI;

    const dim3 GEMM_TC((ND + CTA_M - 1) / CTA_M, RREL);   // (157, 4)
    const int GEMM_BLOCKS_P = (NP + BM - 1) / BM;         // 157
    const int SCAT_BLKS = (E_DDI + 255) / 256;            // 32 edges/warp
    const dim3 SCAT_DDI(SCAT_BLKS, RREL);
    const dim3 CNT_DDI((E_DDI + 255) / 256, RREL);
    const int BIAS_BLKS = (ND * 32 + 255) / 256;

    // --- degrees ---
    cudaMemsetAsync(deg, 0, (size_t)DEG_TOTAL * sizeof(float));
    count_ddi_kernel<<<CNT_DDI, 256>>>(ddi_src, ddi_dst);
    count_pdi_kernel<<<(E_PDI + 255) / 256, 256>>>(pdi_src, pdi_dst);
    finalize_deg_kernel<<<(DEG_TOTAL + 255) / 256, 256>>>();

    // --- Layer 1 ---
    gemm_bf16_rel_kernel<<<GEMM_TC, 512, GEMM_SMEM>>>(x_d, W1, y, ND, 0);
    gemm128_kernel<<<GEMM_BLOCKS_P, 256>>>(x_p, W1_pdi, hp, NP, FP, rn_out_pdi);
    bias_init_kernel<<<BIAS_BLKS, 256>>>(h1, b1, RREL, b1_pdi, ND);
    scatter_pdi_kernel<<<(E_PDI + 255) / 256, 256>>>(pdi_src, pdi_dst);
    scatter_ddi_kernel<<<SCAT_DDI, 256>>>(y, h1, ddi_src, ddi_dst);

    // --- Layer 2 ---  (relu of h1 folded into GEMM A-load)
    gemm_bf16_rel_kernel<<<GEMM_TC, 512, GEMM_SMEM>>>(h1, W2, y, ND, 1);
    bias_init_kernel<<<BIAS_BLKS, 256>>>(h2, b2, RREL, nullptr, ND);
    scatter_ddi_kernel<<<SCAT_DDI, 256>>>(y, h2, ddi_src, ddi_dst);

    // --- Layer 3 ---
    gemm_bf16_rel_kernel<<<GEMM_TC, 512, GEMM_SMEM>>>(h2, W3, y, ND, 1);
    bias_init_kernel<<<BIAS_BLKS, 256>>>(out, b3, RREL, nullptr, ND);
    scatter_ddi_kernel<<<SCAT_DDI, 256>>>(y, out, ddi_src, ddi_dst);
}